// round 1
// baseline (speedup 1.0000x reference)
#include <cuda_runtime.h>

#define VOCAB 30000
#define DIN   512
#define DH    1024
#define DOUT  2047
#define NB    4096
#define SEQ   20

// Scratch (allocation-free rule: __device__ globals)
__device__ float g_H2[(size_t)VOCAB * DH];      // 122.9 MB
__device__ float g_E [(size_t)VOCAB * DOUT];    // 245.6 MB
__device__ float g_invnorm[VOCAB];

static __device__ __forceinline__ unsigned long long pack2(float lo, float hi) {
    unsigned long long r;
    asm("mov.b64 %0, {%1,%2};" : "=l"(r) : "f"(lo), "f"(hi));
    return r;
}
static __device__ __forceinline__ void unpack2(unsigned long long v, float& lo, float& hi) {
    asm("mov.b64 {%0,%1}, %2;" : "=f"(lo), "=f"(hi) : "l"(v));
}
// Packed dual-FMA: 2x fp32 FMA per instruction (Blackwell f32x2 pipe)
static __device__ __forceinline__ void ffma2(unsigned long long& d, unsigned long long a, unsigned long long b) {
    asm("fma.rn.f32x2 %0, %1, %2, %0;" : "+l"(d) : "l"(a), "l"(b));
}

// C[M,N] = act( A'[M,K] @ B[K,N] + cbias[n] ),  A' = FUSE_A ? relu(A + abias[k]) : A
// Tile 128x128x8, 256 threads, 8x8 per thread, f32x2 accumulators.
template<bool FUSE_A, bool RELU_OUT>
__global__ __launch_bounds__(256)
void sgemm_kernel(const float* __restrict__ A, const float* __restrict__ Bm,
                  const float* __restrict__ abias, const float* __restrict__ cbias,
                  float* __restrict__ C, int M, int N, int K)
{
    __shared__ float As[8][128];   // transposed: As[k][m]
    __shared__ float Bs[8][128];

    const int tid = threadIdx.x;
    const int tx  = tid & 15;          // 16 col-groups of 8
    const int ty  = tid >> 4;          // 16 row-groups of 8
    const int m0  = blockIdx.y * 128;
    const int n0  = blockIdx.x * 128;

    // A-tile load mapping: one float4 per thread (128x8 = 1024 elems)
    const int arow = tid >> 1;
    const int akk  = (tid & 1) * 4;
    // B-tile load mapping: 4 scalars per thread (handles N=2047 misalignment)
    const int bkk = tid >> 5;
    const int bn  = (tid & 31) * 4;

    float4 ra;
    float  rb0, rb1, rb2, rb3;

    auto load_tiles = [&](int k0) {
        int gm = m0 + arow;
        if (gm < M) {
            ra = *reinterpret_cast<const float4*>(&A[(size_t)gm * K + k0 + akk]);
            if (FUSE_A) {
                ra.x = fmaxf(ra.x + __ldg(&abias[k0+akk+0]), 0.f);
                ra.y = fmaxf(ra.y + __ldg(&abias[k0+akk+1]), 0.f);
                ra.z = fmaxf(ra.z + __ldg(&abias[k0+akk+2]), 0.f);
                ra.w = fmaxf(ra.w + __ldg(&abias[k0+akk+3]), 0.f);
            }
        } else {
            ra = make_float4(0.f,0.f,0.f,0.f);
        }
        const float* bsrc = &Bm[(size_t)(k0 + bkk) * N];
        int gn = n0 + bn;
        rb0 = (gn+0 < N) ? bsrc[gn+0] : 0.f;
        rb1 = (gn+1 < N) ? bsrc[gn+1] : 0.f;
        rb2 = (gn+2 < N) ? bsrc[gn+2] : 0.f;
        rb3 = (gn+3 < N) ? bsrc[gn+3] : 0.f;
    };
    auto store_tiles = [&]() {
        As[akk+0][arow] = ra.x;
        As[akk+1][arow] = ra.y;
        As[akk+2][arow] = ra.z;
        As[akk+3][arow] = ra.w;
        Bs[bkk][bn+0] = rb0;
        Bs[bkk][bn+1] = rb1;
        Bs[bkk][bn+2] = rb2;
        Bs[bkk][bn+3] = rb3;
    };

    unsigned long long c2[8][4];
    #pragma unroll
    for (int i = 0; i < 8; ++i)
        #pragma unroll
        for (int j = 0; j < 4; ++j) c2[i][j] = 0ull;

    load_tiles(0);
    store_tiles();
    __syncthreads();

    const int ntiles = K >> 3;
    for (int t = 0; t < ntiles; ++t) {
        const bool more = (t + 1 < ntiles);
        if (more) load_tiles((t + 1) << 3);   // prefetch next tile to regs

        #pragma unroll
        for (int kk = 0; kk < 8; ++kk) {
            float4 a0 = *reinterpret_cast<const float4*>(&As[kk][ty*8]);
            float4 a1 = *reinterpret_cast<const float4*>(&As[kk][ty*8+4]);
            const unsigned long long* bp =
                reinterpret_cast<const unsigned long long*>(&Bs[kk][tx*8]);
            unsigned long long b0 = bp[0], b1 = bp[1], b2 = bp[2], b3 = bp[3];
            float av[8] = {a0.x,a0.y,a0.z,a0.w,a1.x,a1.y,a1.z,a1.w};
            #pragma unroll
            for (int i = 0; i < 8; ++i) {
                unsigned long long ai = pack2(av[i], av[i]);
                ffma2(c2[i][0], ai, b0);
                ffma2(c2[i][1], ai, b1);
                ffma2(c2[i][2], ai, b2);
                ffma2(c2[i][3], ai, b3);
            }
        }
        __syncthreads();
        if (more) { store_tiles(); __syncthreads(); }
    }

    #pragma unroll
    for (int i = 0; i < 8; ++i) {
        int gm = m0 + ty*8 + i;
        if (gm >= M) continue;
        float* crow = &C[(size_t)gm * N];
        #pragma unroll
        for (int j = 0; j < 4; ++j) {
            float lo, hi;
            unpack2(c2[i][j], lo, hi);
            int gn = n0 + tx*8 + 2*j;
            if (gn < N) {
                float v = lo + __ldg(&cbias[gn]);
                if (RELU_OUT) v = fmaxf(v, 0.f);
                crow[gn] = v;
            }
            if (gn + 1 < N) {
                float v = hi + __ldg(&cbias[gn+1]);
                if (RELU_OUT) v = fmaxf(v, 0.f);
                crow[gn+1] = v;
            }
        }
    }
}

// 1/max(||E[row]||, eps) per vocab row
__global__ __launch_bounds__(256)
void rownorm_kernel()
{
    const int row = blockIdx.x;
    const float* e = &g_E[(size_t)row * DOUT];
    float ss = 0.f;
    for (int c = threadIdx.x; c < DOUT; c += 256) { float v = e[c]; ss += v * v; }
    #pragma unroll
    for (int o = 16; o; o >>= 1) ss += __shfl_xor_sync(0xffffffffu, ss, o);
    __shared__ float red[8];
    if ((threadIdx.x & 31) == 0) red[threadIdx.x >> 5] = ss;
    __syncthreads();
    if (threadIdx.x == 0) {
        float tot = 0.f;
        #pragma unroll
        for (int w = 0; w < 8; ++w) tot += red[w];
        g_invnorm[row] = 1.f / fmaxf(sqrtf(tot), 1e-12f);
    }
}

// out[b] = sum_{l < len} E[ingrs[b,l]] * invnorm[ingrs[b,l]]
__global__ __launch_bounds__(256)
void gather_kernel(const int* __restrict__ ingrs, const int* __restrict__ lengths,
                   float* __restrict__ out)
{
    const int b = blockIdx.x;
    const int t = threadIdx.x;
    int len = lengths[b];
    if (len > SEQ) len = SEQ;

    float acc[8] = {0.f,0.f,0.f,0.f,0.f,0.f,0.f,0.f};
    for (int l = 0; l < len; ++l) {
        const int id = ingrs[b * SEQ + l];
        const float s = __ldg(&g_invnorm[id]);
        const float* e = &g_E[(size_t)id * DOUT];
        #pragma unroll
        for (int j = 0; j < 8; ++j) {
            int c = t + j * 256;
            if (c < DOUT) acc[j] += e[c] * s;
        }
    }
    #pragma unroll
    for (int j = 0; j < 8; ++j) {
        int c = t + j * 256;
        if (c < DOUT) out[(size_t)b * DOUT + c] = acc[j];
    }
}

extern "C" void kernel_launch(void* const* d_in, const int* in_sizes, int n_in,
                              void* d_out, int out_size)
{
    const int*   ingrs   = (const int*)  d_in[0];
    const int*   lengths = (const int*)  d_in[1];
    const float* W1      = (const float*)d_in[2];
    const float* b1      = (const float*)d_in[3];
    const float* W2      = (const float*)d_in[4];
    const float* b2      = (const float*)d_in[5];
    const float* W3      = (const float*)d_in[6];
    const float* b3      = (const float*)d_in[7];
    float* out = (float*)d_out;

    float *h2p = nullptr, *ep = nullptr;
    cudaGetSymbolAddress((void**)&h2p, g_H2);
    cudaGetSymbolAddress((void**)&ep,  g_E);

    // 1) H2 = relu(relu(W1 + b1) @ W2 + b2)   [30000, 1024]
    dim3 g1(DH / 128, (VOCAB + 127) / 128);
    sgemm_kernel<true, true><<<g1, 256>>>(W1, W2, b1, b2, h2p, VOCAB, DH, DIN);

    // 2) E = H2 @ W3 + b3                     [30000, 2047]
    dim3 g2((DOUT + 127) / 128, (VOCAB + 127) / 128);
    sgemm_kernel<false, false><<<g2, 256>>>(h2p, W3, nullptr, b3, ep, VOCAB, DOUT, DH);

    // 3) per-row inverse norms
    rownorm_kernel<<<VOCAB, 256>>>();

    // 4) masked gather-sum into output
    gather_kernel<<<NB, 256>>>(ingrs, lengths, out);
}

// round 3
// speedup vs baseline: 3.7908x; 3.7908x over previous
#include <cuda_runtime.h>
#include <cuda_bf16.h>
#include <cstdint>

#define VOCAB 30000
#define DIN   512
#define DH    1024
#define DOUT  2047
#define DOUTP 2048
#define NB    4096
#define SEQ   20

// ---------------- scratch (__device__ globals; allocation-free rule) ----------------
__device__ __nv_bfloat16 g_H1h[(size_t)VOCAB * DIN];
__device__ __nv_bfloat16 g_H1l[(size_t)VOCAB * DIN];
__device__ __nv_bfloat16 g_W2Th[(size_t)DH * DIN];     // [1024,512] N-major (K contiguous)
__device__ __nv_bfloat16 g_W2Tl[(size_t)DH * DIN];
__device__ __nv_bfloat16 g_W3Th[(size_t)DOUTP * DH];   // [2048,1024], row 2047 zero
__device__ __nv_bfloat16 g_W3Tl[(size_t)DOUTP * DH];
__device__ __nv_bfloat16 g_H2h[(size_t)VOCAB * DH];
__device__ __nv_bfloat16 g_H2l[(size_t)VOCAB * DH];
__device__ float         g_E[(size_t)VOCAB * DOUTP];   // padded col 2047 == 0
__device__ float         g_invnorm[VOCAB];
__device__ float         g_b3p[DOUTP];

// ---------------- PTX helpers (generic PTX only; works at compute_103) ----------------
static __device__ __forceinline__ uint32_t smem_to_u32(const void* p) {
    uint32_t a;
    asm("{ .reg .u64 t; cvta.to.shared.u64 t, %1; cvt.u32.u64 %0, t; }" : "=r"(a) : "l"(p));
    return a;
}
#define CP16(dst, src) \
    asm volatile("cp.async.cg.shared.global [%0], [%1], 16;" :: "r"(dst), "l"(src) : "memory")
#define CP_COMMIT() asm volatile("cp.async.commit_group;" ::: "memory")
#define CP_WAIT1()  asm volatile("cp.async.wait_group 1;" ::: "memory")

#define LDSM4(r0, r1, r2, r3, addr) \
    asm volatile("ldmatrix.sync.aligned.m8n8.x4.shared.b16 {%0,%1,%2,%3}, [%4];" \
        : "=r"(r0), "=r"(r1), "=r"(r2), "=r"(r3) : "r"(addr))

#define MMA_BF16(d, a0, a1, a2, a3, b0, b1) \
    asm volatile("mma.sync.aligned.m16n8k16.row.col.f32.bf16.bf16.f32 " \
        "{%0,%1,%2,%3},{%4,%5,%6,%7},{%8,%9},{%0,%1,%2,%3};" \
        : "+f"((d)[0]), "+f"((d)[1]), "+f"((d)[2]), "+f"((d)[3]) \
        : "r"(a0), "r"(a1), "r"(a2), "r"(a3), "r"(b0), "r"(b1))

// swizzled byte offset inside a 128-row x 64-byte tile (8KB)
static __device__ __forceinline__ uint32_t sw_off(int row, int ch) {
    return (uint32_t)(row * 64 + ((ch ^ ((row >> 1) & 3)) << 4));
}
static __device__ __forceinline__ uint32_t pack_bf2(float x, float y) {
    __nv_bfloat162 h = __floats2bfloat162_rn(x, y);
    return *reinterpret_cast<uint32_t*>(&h);
}

// ---------------- prep kernels ----------------
__global__ __launch_bounds__(256) void prep_h1(const float* __restrict__ W1,
                                               const float* __restrict__ b1) {
    size_t i4 = ((size_t)blockIdx.x * 256 + threadIdx.x) * 4;
    if (i4 >= (size_t)VOCAB * DIN) return;
    int k = (int)(i4 % DIN);
    float4 w  = *reinterpret_cast<const float4*>(&W1[i4]);
    float4 bb = *reinterpret_cast<const float4*>(&b1[k]);
    float h[4] = { fmaxf(w.x + bb.x, 0.f), fmaxf(w.y + bb.y, 0.f),
                   fmaxf(w.z + bb.z, 0.f), fmaxf(w.w + bb.w, 0.f) };
    __nv_bfloat16 hi[4], lo[4];
#pragma unroll
    for (int j = 0; j < 4; ++j) {
        hi[j] = __float2bfloat16(h[j]);
        lo[j] = __float2bfloat16(h[j] - __bfloat162float(hi[j]));
    }
    *reinterpret_cast<uint2*>(&g_H1h[i4]) = *reinterpret_cast<uint2*>(hi);
    *reinterpret_cast<uint2*>(&g_H1l[i4]) = *reinterpret_cast<uint2*>(lo);
}
__global__ __launch_bounds__(256) void prep_w2t(const float* __restrict__ W2) {
    size_t i = (size_t)blockIdx.x * 256 + threadIdx.x;
    if (i >= (size_t)DH * DIN) return;
    int n = (int)(i / DIN), k = (int)(i % DIN);
    float v = W2[(size_t)k * DH + n];
    __nv_bfloat16 hi = __float2bfloat16(v);
    g_W2Th[i] = hi;
    g_W2Tl[i] = __float2bfloat16(v - __bfloat162float(hi));
}
__global__ __launch_bounds__(256) void prep_w3t(const float* __restrict__ W3) {
    size_t i = (size_t)blockIdx.x * 256 + threadIdx.x;
    if (i >= (size_t)DOUTP * DH) return;
    int n = (int)(i / DH), k = (int)(i % DH);
    float v = (n < DOUT) ? W3[(size_t)k * DOUT + n] : 0.f;
    __nv_bfloat16 hi = __float2bfloat16(v);
    g_W3Th[i] = hi;
    g_W3Tl[i] = __float2bfloat16(v - __bfloat162float(hi));
}
__global__ __launch_bounds__(256) void prep_b3(const float* __restrict__ b3) {
    int i = blockIdx.x * 256 + threadIdx.x;
    if (i < DOUTP) g_b3p[i] = (i < DOUT) ? b3[i] : 0.f;
}

// ---------------- HMMA split-bf16 GEMM ----------------
// C = act(A @ B^T + bias).  A=[M,K] hi/lo bf16, B=[N,K] hi/lo bf16 (K-major).
// CTA tile 128x128, K-chunk 32, 3-stage cp.async pipeline.
// OUT_FP32: fp32 out (ldc-padded). else: relu + bf16 hi/lo split out.
static constexpr int STAGE_BYTES = 32768;                // Ah|Al|Bh|Bl @ 8KB each
static constexpr int GEMM_SMEM   = 3 * STAGE_BYTES;      // 96 KB

template <bool OUT_FP32>
__global__ __launch_bounds__(256, 2)
void hmma_gemm(const __nv_bfloat16* __restrict__ Ah, const __nv_bfloat16* __restrict__ Al,
               const __nv_bfloat16* __restrict__ Bh, const __nv_bfloat16* __restrict__ Bl,
               const float* __restrict__ bias,
               float* __restrict__ Cf, __nv_bfloat16* __restrict__ Ch, __nv_bfloat16* __restrict__ Cl,
               int M, int K, int ldc)
{
    extern __shared__ __align__(128) uint8_t smem[];
    const uint32_t sbase = smem_to_u32(smem);
    const int tid  = threadIdx.x;
    const int lane = tid & 31;
    const int wid  = tid >> 5;
    const int wm   = wid >> 2;          // 0..1  (m block of 64)
    const int wn   = wid & 3;           // 0..3  (n block of 32)
    const int m0   = blockIdx.y * 128;
    const int n0   = blockIdx.x * 128;

    // ldmatrix per-lane addressing: 4 8x8 mats — rows (mat&1)*8+lr, chunk (mat>>1)
    const int lmat  = lane >> 3;
    const int lrow8 = ((lmat & 1) << 3) + (lane & 7);
    const int lchb  = lmat >> 1;

    float acc[4][4][4];
#pragma unroll
    for (int a = 0; a < 4; ++a)
#pragma unroll
        for (int b = 0; b < 4; ++b)
#pragma unroll
            for (int c = 0; c < 4; ++c) acc[a][b][c] = 0.f;

    auto load_stage = [&](int s, int k0) {
        const uint32_t base = sbase + s * STAGE_BYTES;
#pragma unroll
        for (int p = 0; p < 2; ++p) {
            int idx = p * 256 + tid;            // 0..511
            int row = idx >> 2;                 // 0..127
            int ch  = idx & 3;
            uint32_t doff = sw_off(row, ch);
            int gm = m0 + row; if (gm > M - 1) gm = M - 1;   // clamp (rows >= M never stored)
            size_t aoff = (size_t)gm * K + k0 + ch * 8;
            CP16(base +          doff, Ah + aoff);
            CP16(base +  8192 +  doff, Al + aoff);
            size_t boff = (size_t)(n0 + row) * K + k0 + ch * 8;
            CP16(base + 16384 + doff, Bh + boff);
            CP16(base + 24576 + doff, Bl + boff);
        }
        CP_COMMIT();
    };

    auto compute_stage = [&](int s) {
        const uint32_t base = sbase + s * STAGE_BYTES;
#pragma unroll
        for (int kh = 0; kh < 2; ++kh) {
            const int ch = lchb + kh * 2;
            uint32_t ahf[4][4], alf[4][4];
#pragma unroll
            for (int mt = 0; mt < 4; ++mt) {
                int row = wm * 64 + mt * 16 + lrow8;
                uint32_t addr = base + sw_off(row, ch);
                LDSM4(ahf[mt][0], ahf[mt][1], ahf[mt][2], ahf[mt][3], addr);
                LDSM4(alf[mt][0], alf[mt][1], alf[mt][2], alf[mt][3], addr + 8192);
            }
#pragma unroll
            for (int np = 0; np < 2; ++np) {
                int row = wn * 32 + np * 16 + lrow8;
                uint32_t addr = base + 16384 + sw_off(row, ch);
                uint32_t bh[4], bl[4];
                LDSM4(bh[0], bh[1], bh[2], bh[3], addr);
                LDSM4(bl[0], bl[1], bl[2], bl[3], addr + 8192);
#pragma unroll
                for (int mt = 0; mt < 4; ++mt) {
#pragma unroll
                    for (int ni = 0; ni < 2; ++ni) {
                        float* c = acc[mt][np * 2 + ni];
                        MMA_BF16(c, ahf[mt][0], ahf[mt][1], ahf[mt][2], ahf[mt][3], bh[ni], bh[ni + 2]);
                        MMA_BF16(c, ahf[mt][0], ahf[mt][1], ahf[mt][2], ahf[mt][3], bl[ni], bl[ni + 2]);
                        MMA_BF16(c, alf[mt][0], alf[mt][1], alf[mt][2], alf[mt][3], bh[ni], bh[ni + 2]);
                    }
                }
            }
        }
    };

    const int T = K >> 5;
    load_stage(0, 0);
    load_stage(1, 32);
    for (int t = 0; t < T; ++t) {
        CP_WAIT1();
        __syncthreads();
        if (t + 2 < T) load_stage((t + 2) % 3, (t + 2) << 5);
        else           CP_COMMIT();           // keep group count in lockstep for wait_group 1
        compute_stage(t % 3);
    }

    // ---------------- epilogue ----------------
    const int mbase = m0 + wm * 64 + (lane >> 2);
    const int nbase = n0 + wn * 32 + (lane & 3) * 2;
#pragma unroll
    for (int mt = 0; mt < 4; ++mt) {
        int m = mbase + mt * 16;
#pragma unroll
        for (int nt = 0; nt < 4; ++nt) {
            int n = nbase + nt * 8;
            float b0 = __ldg(&bias[n]), b1 = __ldg(&bias[n + 1]);
            float v00 = acc[mt][nt][0] + b0, v01 = acc[mt][nt][1] + b1;
            float v10 = acc[mt][nt][2] + b0, v11 = acc[mt][nt][3] + b1;
            if (OUT_FP32) {
                if (m < M)     *reinterpret_cast<float2*>(&Cf[(size_t)m * ldc + n])       = make_float2(v00, v01);
                if (m + 8 < M) *reinterpret_cast<float2*>(&Cf[(size_t)(m + 8) * ldc + n]) = make_float2(v10, v11);
            } else {
                v00 = fmaxf(v00, 0.f); v01 = fmaxf(v01, 0.f);
                v10 = fmaxf(v10, 0.f); v11 = fmaxf(v11, 0.f);
                if (m < M) {
                    uint32_t h = pack_bf2(v00, v01);
                    __nv_bfloat162 hh = *reinterpret_cast<__nv_bfloat162*>(&h);
                    uint32_t l = pack_bf2(v00 - __bfloat162float(hh.x), v01 - __bfloat162float(hh.y));
                    *reinterpret_cast<uint32_t*>(&Ch[(size_t)m * ldc + n]) = h;
                    *reinterpret_cast<uint32_t*>(&Cl[(size_t)m * ldc + n]) = l;
                }
                if (m + 8 < M) {
                    uint32_t h = pack_bf2(v10, v11);
                    __nv_bfloat162 hh = *reinterpret_cast<__nv_bfloat162*>(&h);
                    uint32_t l = pack_bf2(v10 - __bfloat162float(hh.x), v11 - __bfloat162float(hh.y));
                    *reinterpret_cast<uint32_t*>(&Ch[(size_t)(m + 8) * ldc + n]) = h;
                    *reinterpret_cast<uint32_t*>(&Cl[(size_t)(m + 8) * ldc + n]) = l;
                }
            }
        }
    }
}

// ---------------- norm + gather ----------------
__global__ __launch_bounds__(256) void rownorm_kernel() {
    const int row = blockIdx.x;
    const float4* e = reinterpret_cast<const float4*>(&g_E[(size_t)row * DOUTP]);
    float ss = 0.f;
#pragma unroll
    for (int j = 0; j < 2; ++j) {
        float4 v = __ldg(&e[threadIdx.x + j * 256]);
        ss += v.x * v.x + v.y * v.y + v.z * v.z + v.w * v.w;
    }
#pragma unroll
    for (int o = 16; o; o >>= 1) ss += __shfl_xor_sync(0xffffffffu, ss, o);
    __shared__ float red[8];
    if ((threadIdx.x & 31) == 0) red[threadIdx.x >> 5] = ss;
    __syncthreads();
    if (threadIdx.x == 0) {
        float tot = 0.f;
#pragma unroll
        for (int w = 0; w < 8; ++w) tot += red[w];
        g_invnorm[row] = 1.f / fmaxf(sqrtf(tot), 1e-12f);
    }
}

__global__ __launch_bounds__(256) void gather_kernel(const int* __restrict__ ingrs,
                                                     const int* __restrict__ lengths,
                                                     float* __restrict__ out) {
    const int b = blockIdx.x;
    const int t = threadIdx.x;
    int len = lengths[b];
    if (len > SEQ) len = SEQ;
    float4 a0 = make_float4(0.f, 0.f, 0.f, 0.f), a1 = a0;
    for (int l = 0; l < len; ++l) {
        const int id = ingrs[b * SEQ + l];
        const float s = __ldg(&g_invnorm[id]);
        const float4* e = reinterpret_cast<const float4*>(&g_E[(size_t)id * DOUTP]);
        float4 v0 = __ldg(&e[t]), v1 = __ldg(&e[t + 256]);
        a0.x += v0.x * s; a0.y += v0.y * s; a0.z += v0.z * s; a0.w += v0.w * s;
        a1.x += v1.x * s; a1.y += v1.y * s; a1.z += v1.z * s; a1.w += v1.w * s;
    }
    float* o = out + (size_t)b * DOUT;
    int c0 = t * 4, c1 = (t + 256) * 4;
    o[c0 + 0] = a0.x; o[c0 + 1] = a0.y; o[c0 + 2] = a0.z; o[c0 + 3] = a0.w;
    if (c1 + 0 < DOUT) o[c1 + 0] = a1.x;
    if (c1 + 1 < DOUT) o[c1 + 1] = a1.y;
    if (c1 + 2 < DOUT) o[c1 + 2] = a1.z;
    if (c1 + 3 < DOUT) o[c1 + 3] = a1.w;
}

// ---------------- launch ----------------
extern "C" void kernel_launch(void* const* d_in, const int* in_sizes, int n_in,
                              void* d_out, int out_size)
{
    const int*   ingrs   = (const int*)  d_in[0];
    const int*   lengths = (const int*)  d_in[1];
    const float* W1      = (const float*)d_in[2];
    const float* b1      = (const float*)d_in[3];
    const float* W2      = (const float*)d_in[4];
    const float* b2      = (const float*)d_in[5];
    const float* W3      = (const float*)d_in[6];
    const float* b3      = (const float*)d_in[7];
    float* out = (float*)d_out;

    __nv_bfloat16 *h1h, *h1l, *w2th, *w2tl, *w3th, *w3tl, *h2h, *h2l;
    float *ep, *b3p;
    cudaGetSymbolAddress((void**)&h1h,  g_H1h);
    cudaGetSymbolAddress((void**)&h1l,  g_H1l);
    cudaGetSymbolAddress((void**)&w2th, g_W2Th);
    cudaGetSymbolAddress((void**)&w2tl, g_W2Tl);
    cudaGetSymbolAddress((void**)&w3th, g_W3Th);
    cudaGetSymbolAddress((void**)&w3tl, g_W3Tl);
    cudaGetSymbolAddress((void**)&h2h,  g_H2h);
    cudaGetSymbolAddress((void**)&h2l,  g_H2l);
    cudaGetSymbolAddress((void**)&ep,   g_E);
    cudaGetSymbolAddress((void**)&b3p,  g_b3p);

    cudaFuncSetAttribute(hmma_gemm<true>,  cudaFuncAttributeMaxDynamicSharedMemorySize, GEMM_SMEM);
    cudaFuncSetAttribute(hmma_gemm<false>, cudaFuncAttributeMaxDynamicSharedMemorySize, GEMM_SMEM);

    prep_h1<<<(VOCAB * DIN / 4 + 255) / 256, 256>>>(W1, b1);
    prep_w2t<<<(DH * DIN + 255) / 256, 256>>>(W2);
    prep_w3t<<<((int)((size_t)DOUTP * DH) + 255) / 256, 256>>>(W3);
    prep_b3<<<(DOUTP + 255) / 256, 256>>>(b3);

    // GEMM1: H2 = relu(H1 @ W2^T + b2)   [30000,1024], bf16 hi/lo out
    dim3 g1(DH / 128, (VOCAB + 127) / 128);
    hmma_gemm<false><<<g1, 256, GEMM_SMEM>>>(h1h, h1l, w2th, w2tl, b2,
                                             nullptr, h2h, h2l, VOCAB, DIN, DH);

    // GEMM2: E = H2 @ W3^T + b3          [30000,2048 padded], fp32 out
    dim3 g2(DOUTP / 128, (VOCAB + 127) / 128);
    hmma_gemm<true><<<g2, 256, GEMM_SMEM>>>(h2h, h2l, w3th, w3tl, b3p,
                                            ep, nullptr, nullptr, VOCAB, DH, DOUTP);

    rownorm_kernel<<<VOCAB, 256>>>();
    gather_kernel<<<NB, 256>>>(ingrs, lengths, out);
}

// round 4
// speedup vs baseline: 3.9170x; 1.0333x over previous
#include <cuda_runtime.h>
#include <cuda_bf16.h>
#include <cstdint>

#define VOCAB 30000
#define VROWS 30080          // padded row count for partial-norm slabs
#define DIN   512
#define DH    1024
#define DOUT  2047
#define DOUTP 2048
#define NB    4096
#define SEQ   20
#define NSLAB 64             // 16 N-tiles x 4 wn warps

// ---------------- scratch (__device__ globals; allocation-free rule) ----------------
__device__ __nv_bfloat16 g_H1h[(size_t)VOCAB * DIN];
__device__ __nv_bfloat16 g_H1l[(size_t)VOCAB * DIN];
__device__ __nv_bfloat16 g_W2Th[(size_t)DH * DIN];     // [1024,512] N-major (K contiguous)
__device__ __nv_bfloat16 g_W2Tl[(size_t)DH * DIN];
__device__ __nv_bfloat16 g_W3Th[(size_t)DOUTP * DH];   // [2048,1024], row 2047 zero
__device__ __nv_bfloat16 g_W3Tl[(size_t)DOUTP * DH];
__device__ __nv_bfloat16 g_H2h[(size_t)VOCAB * DH];
__device__ __nv_bfloat16 g_H2l[(size_t)VOCAB * DH];
__device__ float         g_E[(size_t)VOCAB * DOUTP];   // padded col 2047 == 0
__device__ float         g_nsq[(size_t)NSLAB * VROWS]; // per-slab partial sum-of-squares
__device__ float         g_invnorm[VOCAB];

// ---------------- PTX helpers (generic PTX only; valid at compute_103) ----------------
static __device__ __forceinline__ uint32_t smem_to_u32(const void* p) {
    uint32_t a;
    asm("{ .reg .u64 t; cvta.to.shared.u64 t, %1; cvt.u32.u64 %0, t; }" : "=r"(a) : "l"(p));
    return a;
}
#define CP16(dst, src) \
    asm volatile("cp.async.cg.shared.global [%0], [%1], 16;" :: "r"(dst), "l"(src) : "memory")
#define CP_COMMIT() asm volatile("cp.async.commit_group;" ::: "memory")
#define CP_WAIT1()  asm volatile("cp.async.wait_group 1;" ::: "memory")

#define LDSM4(r0, r1, r2, r3, addr) \
    asm volatile("ldmatrix.sync.aligned.m8n8.x4.shared.b16 {%0,%1,%2,%3}, [%4];" \
        : "=r"(r0), "=r"(r1), "=r"(r2), "=r"(r3) : "r"(addr))

#define MMA_BF16(d, a0, a1, a2, a3, b0, b1) \
    asm volatile("mma.sync.aligned.m16n8k16.row.col.f32.bf16.bf16.f32 " \
        "{%0,%1,%2,%3},{%4,%5,%6,%7},{%8,%9},{%0,%1,%2,%3};" \
        : "+f"((d)[0]), "+f"((d)[1]), "+f"((d)[2]), "+f"((d)[3]) \
        : "r"(a0), "r"(a1), "r"(a2), "r"(a3), "r"(b0), "r"(b1))

// swizzled byte offset inside a 128-row x 64-byte tile (8KB)
static __device__ __forceinline__ uint32_t sw_off(int row, int ch) {
    return (uint32_t)(row * 64 + ((ch ^ ((row >> 1) & 3)) << 4));
}
static __device__ __forceinline__ uint32_t pack_bf2(float x, float y) {
    __nv_bfloat162 h = __floats2bfloat162_rn(x, y);
    return *reinterpret_cast<uint32_t*>(&h);
}

// ---------------- prep kernels ----------------
__global__ __launch_bounds__(256) void prep_h1(const float* __restrict__ W1,
                                               const float* __restrict__ b1) {
    size_t i4 = ((size_t)blockIdx.x * 256 + threadIdx.x) * 4;
    if (i4 >= (size_t)VOCAB * DIN) return;
    int k = (int)(i4 % DIN);
    float4 w  = *reinterpret_cast<const float4*>(&W1[i4]);
    float4 bb = *reinterpret_cast<const float4*>(&b1[k]);
    float h[4] = { fmaxf(w.x + bb.x, 0.f), fmaxf(w.y + bb.y, 0.f),
                   fmaxf(w.z + bb.z, 0.f), fmaxf(w.w + bb.w, 0.f) };
    __nv_bfloat16 hi[4], lo[4];
#pragma unroll
    for (int j = 0; j < 4; ++j) {
        hi[j] = __float2bfloat16(h[j]);
        lo[j] = __float2bfloat16(h[j] - __bfloat162float(hi[j]));
    }
    *reinterpret_cast<uint2*>(&g_H1h[i4]) = *reinterpret_cast<uint2*>(hi);
    *reinterpret_cast<uint2*>(&g_H1l[i4]) = *reinterpret_cast<uint2*>(lo);
}

// src [K][N] row-major fp32 -> dst [NP][K] bf16 hi/lo (rows n>=N zero). Tiled transpose.
__global__ __launch_bounds__(256) void transpose_split(const float* __restrict__ src,
                                                       __nv_bfloat16* __restrict__ dh,
                                                       __nv_bfloat16* __restrict__ dl,
                                                       int K, int N) {
    __shared__ float tile[32][33];
    const int tx = threadIdx.x & 31, ty = threadIdx.x >> 5;   // 32 x 8
    const int n0 = blockIdx.x * 32, k0 = blockIdx.y * 32;
#pragma unroll
    for (int i = 0; i < 4; ++i) {
        int k = k0 + ty + i * 8, n = n0 + tx;
        tile[ty + i * 8][tx] = (n < N) ? src[(size_t)k * N + n] : 0.f;
    }
    __syncthreads();
#pragma unroll
    for (int i = 0; i < 4; ++i) {
        int n = n0 + ty + i * 8, k = k0 + tx;
        float v = tile[tx][ty + i * 8];
        __nv_bfloat16 hi = __float2bfloat16(v);
        dh[(size_t)n * K + k] = hi;
        dl[(size_t)n * K + k] = __float2bfloat16(v - __bfloat162float(hi));
    }
}

// ---------------- HMMA split-bf16 GEMM ----------------
// C = act(A @ B^T + bias). CTA tile 128x128, K-chunk 32, 3-stage cp.async pipeline.
static constexpr int STAGE_BYTES = 32768;                // Ah|Al|Bh|Bl @ 8KB each
static constexpr int GEMM_SMEM   = 3 * STAGE_BYTES;      // 96 KB

template <bool OUT_FP32>
__global__ __launch_bounds__(256, 2)
void hmma_gemm(const __nv_bfloat16* __restrict__ Ah, const __nv_bfloat16* __restrict__ Al,
               const __nv_bfloat16* __restrict__ Bh, const __nv_bfloat16* __restrict__ Bl,
               const float* __restrict__ bias,
               float* __restrict__ Cf, __nv_bfloat16* __restrict__ Ch, __nv_bfloat16* __restrict__ Cl,
               int M, int K, int ldc, int nbias)
{
    extern __shared__ __align__(128) uint8_t smem[];
    const uint32_t sbase = smem_to_u32(smem);
    const int tid  = threadIdx.x;
    const int lane = tid & 31;
    const int wid  = tid >> 5;
    const int wm   = wid >> 2;          // 0..1  (m block of 64)
    const int wn   = wid & 3;           // 0..3  (n block of 32)
    const int m0   = blockIdx.y * 128;
    const int n0   = blockIdx.x * 128;

    const int lmat  = lane >> 3;
    const int lrow8 = ((lmat & 1) << 3) + (lane & 7);
    const int lchb  = lmat >> 1;

    float acc[4][4][4];
#pragma unroll
    for (int a = 0; a < 4; ++a)
#pragma unroll
        for (int b = 0; b < 4; ++b)
#pragma unroll
            for (int c = 0; c < 4; ++c) acc[a][b][c] = 0.f;

    auto load_stage = [&](int s, int k0) {
        const uint32_t base = sbase + s * STAGE_BYTES;
#pragma unroll
        for (int p = 0; p < 2; ++p) {
            int idx = p * 256 + tid;
            int row = idx >> 2;
            int ch  = idx & 3;
            uint32_t doff = sw_off(row, ch);
            int gm = m0 + row; if (gm > M - 1) gm = M - 1;   // clamp; rows >= M never stored
            size_t aoff = (size_t)gm * K + k0 + ch * 8;
            CP16(base +         doff, Ah + aoff);
            CP16(base +  8192 + doff, Al + aoff);
            size_t boff = (size_t)(n0 + row) * K + k0 + ch * 8;
            CP16(base + 16384 + doff, Bh + boff);
            CP16(base + 24576 + doff, Bl + boff);
        }
        CP_COMMIT();
    };

    // B-frags held for both n-blocks; A-frags streamed per m-tile (low reg pressure)
    auto compute_stage = [&](int s) {
        const uint32_t base = sbase + s * STAGE_BYTES;
#pragma unroll
        for (int kh = 0; kh < 2; ++kh) {
            const int ch = lchb + kh * 2;
            uint32_t bh[2][4], bl[2][4];
#pragma unroll
            for (int np = 0; np < 2; ++np) {
                uint32_t addr = base + 16384 + sw_off(wn * 32 + np * 16 + lrow8, ch);
                LDSM4(bh[np][0], bh[np][1], bh[np][2], bh[np][3], addr);
                LDSM4(bl[np][0], bl[np][1], bl[np][2], bl[np][3], addr + 8192);
            }
#pragma unroll
            for (int mt = 0; mt < 4; ++mt) {
                uint32_t addr = base + sw_off(wm * 64 + mt * 16 + lrow8, ch);
                uint32_t ah[4], al[4];
                LDSM4(ah[0], ah[1], ah[2], ah[3], addr);
                LDSM4(al[0], al[1], al[2], al[3], addr + 8192);
#pragma unroll
                for (int np = 0; np < 2; ++np) {
#pragma unroll
                    for (int ni = 0; ni < 2; ++ni) {
                        float* c = acc[mt][np * 2 + ni];
                        MMA_BF16(c, ah[0], ah[1], ah[2], ah[3], bh[np][ni], bh[np][ni + 2]);
                        MMA_BF16(c, ah[0], ah[1], ah[2], ah[3], bl[np][ni], bl[np][ni + 2]);
                        MMA_BF16(c, al[0], al[1], al[2], al[3], bh[np][ni], bh[np][ni + 2]);
                    }
                }
            }
        }
    };

    const int T = K >> 5;
    load_stage(0, 0);
    load_stage(1, 32);
    for (int t = 0; t < T; ++t) {
        CP_WAIT1();
        __syncthreads();
        if (t + 2 < T) load_stage((t + 2) % 3, (t + 2) << 5);
        else           CP_COMMIT();           // keep group count aligned for wait_group 1
        compute_stage(t % 3);
    }

    // ---------------- epilogue ----------------
    const int mbase = m0 + wm * 64 + (lane >> 2);
    const int nbase = n0 + wn * 32 + (lane & 3) * 2;
#pragma unroll
    for (int mt = 0; mt < 4; ++mt) {
        int m = mbase + mt * 16;
        float s0 = 0.f, s1 = 0.f;
#pragma unroll
        for (int nt = 0; nt < 4; ++nt) {
            int n = nbase + nt * 8;
            float b0 = (n     < nbias) ? __ldg(&bias[n])     : 0.f;
            float b1 = (n + 1 < nbias) ? __ldg(&bias[n + 1]) : 0.f;
            float v00 = acc[mt][nt][0] + b0, v01 = acc[mt][nt][1] + b1;
            float v10 = acc[mt][nt][2] + b0, v11 = acc[mt][nt][3] + b1;
            if (OUT_FP32) {
                s0 += v00 * v00 + v01 * v01;
                s1 += v10 * v10 + v11 * v11;
                if (m < M)     *reinterpret_cast<float2*>(&Cf[(size_t)m * ldc + n])       = make_float2(v00, v01);
                if (m + 8 < M) *reinterpret_cast<float2*>(&Cf[(size_t)(m + 8) * ldc + n]) = make_float2(v10, v11);
            } else {
                v00 = fmaxf(v00, 0.f); v01 = fmaxf(v01, 0.f);
                v10 = fmaxf(v10, 0.f); v11 = fmaxf(v11, 0.f);
                if (m < M) {
                    uint32_t h = pack_bf2(v00, v01);
                    __nv_bfloat162 hh = *reinterpret_cast<__nv_bfloat162*>(&h);
                    uint32_t l = pack_bf2(v00 - __bfloat162float(hh.x), v01 - __bfloat162float(hh.y));
                    *reinterpret_cast<uint32_t*>(&Ch[(size_t)m * ldc + n]) = h;
                    *reinterpret_cast<uint32_t*>(&Cl[(size_t)m * ldc + n]) = l;
                }
                if (m + 8 < M) {
                    uint32_t h = pack_bf2(v10, v11);
                    __nv_bfloat162 hh = *reinterpret_cast<__nv_bfloat162*>(&h);
                    uint32_t l = pack_bf2(v10 - __bfloat162float(hh.x), v11 - __bfloat162float(hh.y));
                    *reinterpret_cast<uint32_t*>(&Ch[(size_t)(m + 8) * ldc + n]) = h;
                    *reinterpret_cast<uint32_t*>(&Cl[(size_t)(m + 8) * ldc + n]) = l;
                }
            }
        }
        if (OUT_FP32) {
            // reduce sum-of-squares across the 4 lanes covering this row (lane&3)
            s0 += __shfl_xor_sync(0xffffffffu, s0, 1);
            s0 += __shfl_xor_sync(0xffffffffu, s0, 2);
            s1 += __shfl_xor_sync(0xffffffffu, s1, 1);
            s1 += __shfl_xor_sync(0xffffffffu, s1, 2);
            if ((lane & 3) == 0) {
                size_t slab = (size_t)(blockIdx.x * 4 + wn) * VROWS;
                if (m < M)     g_nsq[slab + m]     = s0;
                if (m + 8 < M) g_nsq[slab + m + 8] = s1;
            }
        }
    }
}

// ---------------- norm finalize + gather ----------------
__global__ __launch_bounds__(256) void rsqrt_kernel() {
    int r = blockIdx.x * 256 + threadIdx.x;
    if (r >= VOCAB) return;
    float tot = 0.f;
#pragma unroll
    for (int s = 0; s < NSLAB; ++s) tot += g_nsq[(size_t)s * VROWS + r];
    g_invnorm[r] = 1.f / fmaxf(sqrtf(tot), 1e-12f);
}

__global__ __launch_bounds__(256) void gather_kernel(const int* __restrict__ ingrs,
                                                     const int* __restrict__ lengths,
                                                     float* __restrict__ out) {
    __shared__ const float4* sptr[SEQ];
    __shared__ float sscl[SEQ];
    const int b = blockIdx.x;
    const int t = threadIdx.x;
    if (t < SEQ) {
        int id = ingrs[b * SEQ + t];
        sptr[t] = reinterpret_cast<const float4*>(&g_E[(size_t)id * DOUTP]);
        sscl[t] = g_invnorm[id];
    }
    __syncthreads();
    int len = lengths[b];
    if (len > SEQ) len = SEQ;

    float4 a0 = make_float4(0.f, 0.f, 0.f, 0.f), a1 = a0;
    int l = 0;
    for (; l + 2 <= len; l += 2) {
        const float4* e0 = sptr[l];     float s0 = sscl[l];
        const float4* e1 = sptr[l + 1]; float s1 = sscl[l + 1];
        float4 u0 = __ldg(&e0[t]), u1 = __ldg(&e0[t + 256]);
        float4 w0 = __ldg(&e1[t]), w1 = __ldg(&e1[t + 256]);
        a0.x += u0.x * s0; a0.y += u0.y * s0; a0.z += u0.z * s0; a0.w += u0.w * s0;
        a1.x += u1.x * s0; a1.y += u1.y * s0; a1.z += u1.z * s0; a1.w += u1.w * s0;
        a0.x += w0.x * s1; a0.y += w0.y * s1; a0.z += w0.z * s1; a0.w += w0.w * s1;
        a1.x += w1.x * s1; a1.y += w1.y * s1; a1.z += w1.z * s1; a1.w += w1.w * s1;
    }
    if (l < len) {
        const float4* e0 = sptr[l]; float s0 = sscl[l];
        float4 u0 = __ldg(&e0[t]), u1 = __ldg(&e0[t + 256]);
        a0.x += u0.x * s0; a0.y += u0.y * s0; a0.z += u0.z * s0; a0.w += u0.w * s0;
        a1.x += u1.x * s0; a1.y += u1.y * s0; a1.z += u1.z * s0; a1.w += u1.w * s0;
    }
    float* o = out + (size_t)b * DOUT;
    int c0 = t * 4, c1 = (t + 256) * 4;
    o[c0 + 0] = a0.x; o[c0 + 1] = a0.y; o[c0 + 2] = a0.z; o[c0 + 3] = a0.w;
    if (c1 + 0 < DOUT) o[c1 + 0] = a1.x;
    if (c1 + 1 < DOUT) o[c1 + 1] = a1.y;
    if (c1 + 2 < DOUT) o[c1 + 2] = a1.z;
    if (c1 + 3 < DOUT) o[c1 + 3] = a1.w;
}

// ---------------- launch ----------------
extern "C" void kernel_launch(void* const* d_in, const int* in_sizes, int n_in,
                              void* d_out, int out_size)
{
    const int*   ingrs   = (const int*)  d_in[0];
    const int*   lengths = (const int*)  d_in[1];
    const float* W1      = (const float*)d_in[2];
    const float* b1      = (const float*)d_in[3];
    const float* W2      = (const float*)d_in[4];
    const float* b2      = (const float*)d_in[5];
    const float* W3      = (const float*)d_in[6];
    const float* b3      = (const float*)d_in[7];
    float* out = (float*)d_out;

    __nv_bfloat16 *h1h, *h1l, *w2th, *w2tl, *w3th, *w3tl, *h2h, *h2l;
    float *ep;
    cudaGetSymbolAddress((void**)&h1h,  g_H1h);
    cudaGetSymbolAddress((void**)&h1l,  g_H1l);
    cudaGetSymbolAddress((void**)&w2th, g_W2Th);
    cudaGetSymbolAddress((void**)&w2tl, g_W2Tl);
    cudaGetSymbolAddress((void**)&w3th, g_W3Th);
    cudaGetSymbolAddress((void**)&w3tl, g_W3Tl);
    cudaGetSymbolAddress((void**)&h2h,  g_H2h);
    cudaGetSymbolAddress((void**)&h2l,  g_H2l);
    cudaGetSymbolAddress((void**)&ep,   g_E);

    cudaFuncSetAttribute(hmma_gemm<true>,  cudaFuncAttributeMaxDynamicSharedMemorySize, GEMM_SMEM);
    cudaFuncSetAttribute(hmma_gemm<false>, cudaFuncAttributeMaxDynamicSharedMemorySize, GEMM_SMEM);

    prep_h1<<<(VOCAB * DIN / 4 + 255) / 256, 256>>>(W1, b1);
    transpose_split<<<dim3(DH / 32, DIN / 32), 256>>>(W2, w2th, w2tl, DIN, DH);
    transpose_split<<<dim3(DOUTP / 32, DH / 32), 256>>>(W3, w3th, w3tl, DH, DOUT);

    // GEMM1: H2 = relu(H1 @ W2^T + b2)   [30000,1024], bf16 hi/lo out
    dim3 g1(DH / 128, (VOCAB + 127) / 128);
    hmma_gemm<false><<<g1, 256, GEMM_SMEM>>>(h1h, h1l, w2th, w2tl, b2,
                                             nullptr, h2h, h2l, VOCAB, DIN, DH, DH);

    // GEMM2: E = H2 @ W3^T + b3          [30000,2048 padded], fp32 out + norm partials
    dim3 g2(DOUTP / 128, (VOCAB + 127) / 128);
    hmma_gemm<true><<<g2, 256, GEMM_SMEM>>>(h2h, h2l, w3th, w3tl, b3,
                                            ep, nullptr, nullptr, VOCAB, DH, DOUTP, DOUT);

    rsqrt_kernel<<<(VOCAB + 255) / 256, 256>>>();
    gather_kernel<<<NB, 256>>>(ingrs, lengths, out);
}

// round 5
// speedup vs baseline: 5.8744x; 1.4997x over previous
#include <cuda_runtime.h>
#include <cuda_fp16.h>
#include <cstdint>

#define VOCAB 30000
#define VROWS 30080          // padded row count for partial-norm slabs
#define DIN   512
#define DH    1024
#define DOUT  2047
#define DOUTP 2048
#define NB    4096
#define SEQ   20
#define NSLAB 64             // 16 N-tiles x 4 wn warps

// ---------------- scratch (__device__ globals; allocation-free rule) ----------------
__device__ __half g_H1f[(size_t)VOCAB * DIN];      // fp16 single
__device__ __half g_W2Th[(size_t)DH * DIN];        // [1024,512] N-major, hi
__device__ __half g_W2Tl[(size_t)DH * DIN];        // lo
__device__ __half g_W3Th[(size_t)DOUTP * DH];      // [2048,1024], row 2047 zero
__device__ __half g_W3Tl[(size_t)DOUTP * DH];
__device__ __half g_H2f[(size_t)VOCAB * DH];       // fp16 single
__device__ float  g_E[(size_t)VOCAB * DOUTP];      // padded col 2047 == 0
__device__ float  g_nsq[(size_t)NSLAB * VROWS];    // per-slab partial sum-of-squares
__device__ float  g_invnorm[VOCAB];

// ---------------- PTX helpers (generic PTX only; valid at compute_103) ----------------
static __device__ __forceinline__ uint32_t smem_to_u32(const void* p) {
    uint32_t a;
    asm("{ .reg .u64 t; cvta.to.shared.u64 t, %1; cvt.u32.u64 %0, t; }" : "=r"(a) : "l"(p));
    return a;
}
#define CP16(dst, src) \
    asm volatile("cp.async.cg.shared.global [%0], [%1], 16;" :: "r"(dst), "l"(src) : "memory")
#define CP_COMMIT() asm volatile("cp.async.commit_group;" ::: "memory")
#define CP_WAIT2()  asm volatile("cp.async.wait_group 2;" ::: "memory")

#define LDSM4(r0, r1, r2, r3, addr) \
    asm volatile("ldmatrix.sync.aligned.m8n8.x4.shared.b16 {%0,%1,%2,%3}, [%4];" \
        : "=r"(r0), "=r"(r1), "=r"(r2), "=r"(r3) : "r"(addr))

#define MMA_F16(d, a0, a1, a2, a3, b0, b1) \
    asm volatile("mma.sync.aligned.m16n8k16.row.col.f32.f16.f16.f32 " \
        "{%0,%1,%2,%3},{%4,%5,%6,%7},{%8,%9},{%0,%1,%2,%3};" \
        : "+f"((d)[0]), "+f"((d)[1]), "+f"((d)[2]), "+f"((d)[3]) \
        : "r"(a0), "r"(a1), "r"(a2), "r"(a3), "r"(b0), "r"(b1))

// swizzled byte offset inside a 128-row x 64-byte tile (8KB)
static __device__ __forceinline__ uint32_t sw_off(int row, int ch) {
    return (uint32_t)(row * 64 + ((ch ^ ((row >> 1) & 3)) << 4));
}
static __device__ __forceinline__ uint32_t pack_h2(float x, float y) {
    __half2 h = __floats2half2_rn(x, y);
    return *reinterpret_cast<uint32_t*>(&h);
}

// ---------------- prep kernels ----------------
__global__ __launch_bounds__(256) void prep_h1(const float* __restrict__ W1,
                                               const float* __restrict__ b1) {
    size_t i4 = ((size_t)blockIdx.x * 256 + threadIdx.x) * 4;
    if (i4 >= (size_t)VOCAB * DIN) return;
    int k = (int)(i4 % DIN);
    float4 w  = *reinterpret_cast<const float4*>(&W1[i4]);
    float4 bb = *reinterpret_cast<const float4*>(&b1[k]);
    __half h[4] = { __float2half_rn(fmaxf(w.x + bb.x, 0.f)),
                    __float2half_rn(fmaxf(w.y + bb.y, 0.f)),
                    __float2half_rn(fmaxf(w.z + bb.z, 0.f)),
                    __float2half_rn(fmaxf(w.w + bb.w, 0.f)) };
    *reinterpret_cast<uint2*>(&g_H1f[i4]) = *reinterpret_cast<uint2*>(h);
}

// src [K][N] row-major fp32 -> dst [NP][K] fp16 hi/lo (rows n>=N zero). Tiled transpose.
__global__ __launch_bounds__(256) void transpose_split(const float* __restrict__ src,
                                                       __half* __restrict__ dh,
                                                       __half* __restrict__ dl,
                                                       int K, int N) {
    __shared__ float tile[32][33];
    const int tx = threadIdx.x & 31, ty = threadIdx.x >> 5;   // 32 x 8
    const int n0 = blockIdx.x * 32, k0 = blockIdx.y * 32;
#pragma unroll
    for (int i = 0; i < 4; ++i) {
        int k = k0 + ty + i * 8, n = n0 + tx;
        tile[ty + i * 8][tx] = (n < N) ? src[(size_t)k * N + n] : 0.f;
    }
    __syncthreads();
#pragma unroll
    for (int i = 0; i < 4; ++i) {
        int n = n0 + ty + i * 8, k = k0 + tx;
        float v = tile[tx][ty + i * 8];
        __half hi = __float2half_rn(v);
        dh[(size_t)n * K + k] = hi;
        dl[(size_t)n * K + k] = __float2half_rn(v - __half2float(hi));
    }
}

// ---------------- HMMA 2-product fp16 GEMM ----------------
// C = act(A @ B^T + bias). A=[M,K] fp16, B=[N,K] fp16 hi/lo (K-major).
// CTA tile 128x128, K-chunk 32, 4-stage cp.async pipeline (A|Bh|Bl @ 8KB).
static constexpr int STAGE_BYTES = 24576;
static constexpr int GEMM_SMEM   = 4 * STAGE_BYTES;      // 96 KB

template <bool OUT_FP32>
__global__ __launch_bounds__(256, 2)
void hmma_gemm(const __half* __restrict__ Af,
               const __half* __restrict__ Bh, const __half* __restrict__ Bl,
               const float* __restrict__ bias,
               float* __restrict__ Cf, __half* __restrict__ Ch,
               int M, int K, int ldc, int nbias)
{
    extern __shared__ __align__(128) uint8_t smem[];
    const uint32_t sbase = smem_to_u32(smem);
    const int tid  = threadIdx.x;
    const int lane = tid & 31;
    const int wid  = tid >> 5;
    const int wm   = wid >> 2;          // 0..1  (m block of 64)
    const int wn   = wid & 3;           // 0..3  (n block of 32)
    const int m0   = blockIdx.y * 128;
    const int n0   = blockIdx.x * 128;

    const int lmat  = lane >> 3;
    const int lrow8 = ((lmat & 1) << 3) + (lane & 7);
    const int lchb  = lmat >> 1;

    float acc[4][4][4];
#pragma unroll
    for (int a = 0; a < 4; ++a)
#pragma unroll
        for (int b = 0; b < 4; ++b)
#pragma unroll
            for (int c = 0; c < 4; ++c) acc[a][b][c] = 0.f;

    auto load_stage = [&](int s, int k0) {
        const uint32_t base = sbase + s * STAGE_BYTES;
#pragma unroll
        for (int p = 0; p < 2; ++p) {
            int idx = p * 256 + tid;            // 0..511
            int row = idx >> 2;
            int ch  = idx & 3;
            uint32_t doff = sw_off(row, ch);
            int gm = m0 + row; if (gm > M - 1) gm = M - 1;   // clamp; rows >= M never stored
            CP16(base +         doff, Af + (size_t)gm * K + k0 + ch * 8);
            size_t boff = (size_t)(n0 + row) * K + k0 + ch * 8;
            CP16(base +  8192 + doff, Bh + boff);
            CP16(base + 16384 + doff, Bl + boff);
        }
        CP_COMMIT();
    };

    // all frags for a k-half preloaded, then 32 back-to-back MMAs
    auto compute_stage = [&](int s) {
        const uint32_t base = sbase + s * STAGE_BYTES;
#pragma unroll
        for (int kh = 0; kh < 2; ++kh) {
            const int ch = lchb + kh * 2;
            uint32_t bh[2][4], bl[2][4], af[4][4];
#pragma unroll
            for (int np = 0; np < 2; ++np) {
                uint32_t addr = base + 8192 + sw_off(wn * 32 + np * 16 + lrow8, ch);
                LDSM4(bh[np][0], bh[np][1], bh[np][2], bh[np][3], addr);
                LDSM4(bl[np][0], bl[np][1], bl[np][2], bl[np][3], addr + 8192);
            }
#pragma unroll
            for (int mt = 0; mt < 4; ++mt) {
                uint32_t addr = base + sw_off(wm * 64 + mt * 16 + lrow8, ch);
                LDSM4(af[mt][0], af[mt][1], af[mt][2], af[mt][3], addr);
            }
#pragma unroll
            for (int mt = 0; mt < 4; ++mt) {
#pragma unroll
                for (int np = 0; np < 2; ++np) {
#pragma unroll
                    for (int ni = 0; ni < 2; ++ni) {
                        float* c = acc[mt][np * 2 + ni];
                        MMA_F16(c, af[mt][0], af[mt][1], af[mt][2], af[mt][3], bh[np][ni], bh[np][ni + 2]);
                        MMA_F16(c, af[mt][0], af[mt][1], af[mt][2], af[mt][3], bl[np][ni], bl[np][ni + 2]);
                    }
                }
            }
        }
    };

    const int T = K >> 5;                 // K >= 512 -> T >= 16
    load_stage(0, 0);
    load_stage(1, 32);
    load_stage(2, 64);
    for (int t = 0; t < T; ++t) {
        CP_WAIT2();
        __syncthreads();
        if (t + 3 < T) load_stage((t + 3) & 3, (t + 3) << 5);
        else           CP_COMMIT();       // keep group count aligned for wait_group 2
        compute_stage(t & 3);
    }

    // ---------------- epilogue ----------------
    const int mbase = m0 + wm * 64 + (lane >> 2);
    const int nbase = n0 + wn * 32 + (lane & 3) * 2;
#pragma unroll
    for (int mt = 0; mt < 4; ++mt) {
        int m = mbase + mt * 16;
        float s0 = 0.f, s1 = 0.f;
#pragma unroll
        for (int nt = 0; nt < 4; ++nt) {
            int n = nbase + nt * 8;
            float b0 = (n     < nbias) ? __ldg(&bias[n])     : 0.f;
            float b1 = (n + 1 < nbias) ? __ldg(&bias[n + 1]) : 0.f;
            float v00 = acc[mt][nt][0] + b0, v01 = acc[mt][nt][1] + b1;
            float v10 = acc[mt][nt][2] + b0, v11 = acc[mt][nt][3] + b1;
            if (OUT_FP32) {
                s0 += v00 * v00 + v01 * v01;
                s1 += v10 * v10 + v11 * v11;
                if (m < M)     *reinterpret_cast<float2*>(&Cf[(size_t)m * ldc + n])       = make_float2(v00, v01);
                if (m + 8 < M) *reinterpret_cast<float2*>(&Cf[(size_t)(m + 8) * ldc + n]) = make_float2(v10, v11);
            } else {
                if (m < M)
                    *reinterpret_cast<uint32_t*>(&Ch[(size_t)m * ldc + n]) =
                        pack_h2(fmaxf(v00, 0.f), fmaxf(v01, 0.f));
                if (m + 8 < M)
                    *reinterpret_cast<uint32_t*>(&Ch[(size_t)(m + 8) * ldc + n]) =
                        pack_h2(fmaxf(v10, 0.f), fmaxf(v11, 0.f));
            }
        }
        if (OUT_FP32) {
            s0 += __shfl_xor_sync(0xffffffffu, s0, 1);
            s0 += __shfl_xor_sync(0xffffffffu, s0, 2);
            s1 += __shfl_xor_sync(0xffffffffu, s1, 1);
            s1 += __shfl_xor_sync(0xffffffffu, s1, 2);
            if ((lane & 3) == 0) {
                size_t slab = (size_t)(blockIdx.x * 4 + wn) * VROWS;
                if (m < M)     g_nsq[slab + m]     = s0;
                if (m + 8 < M) g_nsq[slab + m + 8] = s1;
            }
        }
    }
}

// ---------------- norm finalize + gather ----------------
__global__ __launch_bounds__(256) void rsqrt_kernel() {
    int r = blockIdx.x * 256 + threadIdx.x;
    if (r >= VOCAB) return;
    float tot = 0.f;
#pragma unroll
    for (int s = 0; s < NSLAB; ++s) tot += g_nsq[(size_t)s * VROWS + r];
    g_invnorm[r] = 1.f / fmaxf(sqrtf(tot), 1e-12f);
}

__global__ __launch_bounds__(256) void gather_kernel(const int* __restrict__ ingrs,
                                                     const int* __restrict__ lengths,
                                                     float* __restrict__ out) {
    __shared__ const float4* sptr[SEQ];
    __shared__ float sscl[SEQ];
    const int b = blockIdx.x;
    const int t = threadIdx.x;
    if (t < SEQ) {
        int id = ingrs[b * SEQ + t];
        sptr[t] = reinterpret_cast<const float4*>(&g_E[(size_t)id * DOUTP]);
        sscl[t] = g_invnorm[id];
    }
    __syncthreads();
    int len = lengths[b];
    if (len > SEQ) len = SEQ;

    float4 a0 = make_float4(0.f, 0.f, 0.f, 0.f), a1 = a0;
    int l = 0;
    for (; l + 2 <= len; l += 2) {
        const float4* e0 = sptr[l];     float s0 = sscl[l];
        const float4* e1 = sptr[l + 1]; float s1 = sscl[l + 1];
        float4 u0 = __ldg(&e0[t]), u1 = __ldg(&e0[t + 256]);
        float4 w0 = __ldg(&e1[t]), w1 = __ldg(&e1[t + 256]);
        a0.x += u0.x * s0; a0.y += u0.y * s0; a0.z += u0.z * s0; a0.w += u0.w * s0;
        a1.x += u1.x * s0; a1.y += u1.y * s0; a1.z += u1.z * s0; a1.w += u1.w * s0;
        a0.x += w0.x * s1; a0.y += w0.y * s1; a0.z += w0.z * s1; a0.w += w0.w * s1;
        a1.x += w1.x * s1; a1.y += w1.y * s1; a1.z += w1.z * s1; a1.w += w1.w * s1;
    }
    if (l < len) {
        const float4* e0 = sptr[l]; float s0 = sscl[l];
        float4 u0 = __ldg(&e0[t]), u1 = __ldg(&e0[t + 256]);
        a0.x += u0.x * s0; a0.y += u0.y * s0; a0.z += u0.z * s0; a0.w += u0.w * s0;
        a1.x += u1.x * s0; a1.y += u1.y * s0; a1.z += u1.z * s0; a1.w += u1.w * s0;
    }
    float* o = out + (size_t)b * DOUT;
    int c0 = t * 4, c1 = (t + 256) * 4;
    o[c0 + 0] = a0.x; o[c0 + 1] = a0.y; o[c0 + 2] = a0.z; o[c0 + 3] = a0.w;
    if (c1 + 0 < DOUT) o[c1 + 0] = a1.x;
    if (c1 + 1 < DOUT) o[c1 + 1] = a1.y;
    if (c1 + 2 < DOUT) o[c1 + 2] = a1.z;
    if (c1 + 3 < DOUT) o[c1 + 3] = a1.w;
}

// ---------------- launch ----------------
extern "C" void kernel_launch(void* const* d_in, const int* in_sizes, int n_in,
                              void* d_out, int out_size)
{
    const int*   ingrs   = (const int*)  d_in[0];
    const int*   lengths = (const int*)  d_in[1];
    const float* W1      = (const float*)d_in[2];
    const float* b1      = (const float*)d_in[3];
    const float* W2      = (const float*)d_in[4];
    const float* b2      = (const float*)d_in[5];
    const float* W3      = (const float*)d_in[6];
    const float* b3      = (const float*)d_in[7];
    float* out = (float*)d_out;

    __half *h1f, *w2th, *w2tl, *w3th, *w3tl, *h2f;
    float *ep;
    cudaGetSymbolAddress((void**)&h1f,  g_H1f);
    cudaGetSymbolAddress((void**)&w2th, g_W2Th);
    cudaGetSymbolAddress((void**)&w2tl, g_W2Tl);
    cudaGetSymbolAddress((void**)&w3th, g_W3Th);
    cudaGetSymbolAddress((void**)&w3tl, g_W3Tl);
    cudaGetSymbolAddress((void**)&h2f,  g_H2f);
    cudaGetSymbolAddress((void**)&ep,   g_E);

    cudaFuncSetAttribute(hmma_gemm<true>,  cudaFuncAttributeMaxDynamicSharedMemorySize, GEMM_SMEM);
    cudaFuncSetAttribute(hmma_gemm<false>, cudaFuncAttributeMaxDynamicSharedMemorySize, GEMM_SMEM);

    prep_h1<<<(VOCAB * DIN / 4 + 255) / 256, 256>>>(W1, b1);
    transpose_split<<<dim3(DH / 32, DIN / 32), 256>>>(W2, w2th, w2tl, DIN, DH);
    transpose_split<<<dim3(DOUTP / 32, DH / 32), 256>>>(W3, w3th, w3tl, DH, DOUT);

    // GEMM1: H2 = relu(H1 @ W2^T + b2)   [30000,1024], fp16 out
    dim3 g1(DH / 128, (VOCAB + 127) / 128);
    hmma_gemm<false><<<g1, 256, GEMM_SMEM>>>(h1f, w2th, w2tl, b2,
                                             nullptr, h2f, VOCAB, DIN, DH, DH);

    // GEMM2: E = H2 @ W3^T + b3          [30000,2048 padded], fp32 out + norm partials
    dim3 g2(DOUTP / 128, (VOCAB + 127) / 128);
    hmma_gemm<true><<<g2, 256, GEMM_SMEM>>>(h2f, w3th, w3tl, b3,
                                            ep, nullptr, VOCAB, DH, DOUTP, DOUT);

    rsqrt_kernel<<<(VOCAB + 255) / 256, 256>>>();
    gather_kernel<<<NB, 256>>>(ingrs, lengths, out);
}

// round 7
// speedup vs baseline: 10.2143x; 1.7388x over previous
#include <cuda_runtime.h>
#include <cuda_fp16.h>
#include <cstdint>

#define VOCAB 30000
#define VROWS 30080          // padded row count for partial-norm slabs
#define DIN   512
#define DH    1024
#define DOUT  2047
#define DOUTP 2048
#define NB    4096
#define SEQ   20
#define NSLAB 64             // 16 N-tiles x 4 wn warps

// ---------------- scratch (__device__ globals; allocation-free rule) ----------------
__device__ __half g_H1f[(size_t)VOCAB * DIN];      // fp16
__device__ __half g_W2T[(size_t)DH * DIN];         // [1024,512] N-major fp16
__device__ __half g_W3T[(size_t)DOUTP * DH];       // [2048,1024] fp16, row 2047 zero
__device__ __half g_H2f[(size_t)VOCAB * DH];       // fp16
__device__ __half g_Eh[(size_t)VOCAB * DOUTP];     // fp16 E, padded col 2047 == 0
__device__ float  g_nsq[(size_t)NSLAB * VROWS];    // per-slab partial sum-of-squares (fp32)
__device__ float  g_invnorm[VOCAB];

// ---------------- PTX helpers (generic PTX only; valid at compute_103) ----------------
static __device__ __forceinline__ uint32_t smem_to_u32(const void* p) {
    uint32_t a;
    asm("{ .reg .u64 t; cvta.to.shared.u64 t, %1; cvt.u32.u64 %0, t; }" : "=r"(a) : "l"(p));
    return a;
}
#define CP16(dst, src) \
    asm volatile("cp.async.cg.shared.global [%0], [%1], 16;" :: "r"(dst), "l"(src) : "memory")
#define CP_COMMIT() asm volatile("cp.async.commit_group;" ::: "memory")
#define CP_WAIT1()  asm volatile("cp.async.wait_group 1;" ::: "memory")

#define LDSM4(r0, r1, r2, r3, addr) \
    asm volatile("ldmatrix.sync.aligned.m8n8.x4.shared.b16 {%0,%1,%2,%3}, [%4];" \
        : "=r"(r0), "=r"(r1), "=r"(r2), "=r"(r3) : "r"(addr))

#define MMA_F16(d, a0, a1, a2, a3, b0, b1) \
    asm volatile("mma.sync.aligned.m16n8k16.row.col.f32.f16.f16.f32 " \
        "{%0,%1,%2,%3},{%4,%5,%6,%7},{%8,%9},{%0,%1,%2,%3};" \
        : "+f"((d)[0]), "+f"((d)[1]), "+f"((d)[2]), "+f"((d)[3]) \
        : "r"(a0), "r"(a1), "r"(a2), "r"(a3), "r"(b0), "r"(b1))

// swizzled byte offset inside a 128-row x 128-byte tile (16KB): 8 chunks of 16B per row
static __device__ __forceinline__ uint32_t swq(int row, int ch) {
    return (uint32_t)(row * 128 + ((ch ^ (row & 7)) << 4));
}
static __device__ __forceinline__ uint32_t pack_h2(float x, float y) {
    __half2 h = __floats2half2_rn(x, y);
    return *reinterpret_cast<uint32_t*>(&h);
}

// ---------------- prep kernels ----------------
__global__ __launch_bounds__(256) void prep_h1(const float* __restrict__ W1,
                                               const float* __restrict__ b1) {
    size_t i4 = ((size_t)blockIdx.x * 256 + threadIdx.x) * 4;
    if (i4 >= (size_t)VOCAB * DIN) return;
    int k = (int)(i4 % DIN);
    float4 w  = *reinterpret_cast<const float4*>(&W1[i4]);
    float4 bb = *reinterpret_cast<const float4*>(&b1[k]);
    __half h[4] = { __float2half_rn(fmaxf(w.x + bb.x, 0.f)),
                    __float2half_rn(fmaxf(w.y + bb.y, 0.f)),
                    __float2half_rn(fmaxf(w.z + bb.z, 0.f)),
                    __float2half_rn(fmaxf(w.w + bb.w, 0.f)) };
    *reinterpret_cast<uint2*>(&g_H1f[i4]) = *reinterpret_cast<uint2*>(h);
}

// src [K][N] row-major fp32 -> dst [NP][K] fp16 (rows n>=N zero). Tiled transpose.
__global__ __launch_bounds__(256) void transpose_f16(const float* __restrict__ src,
                                                     __half* __restrict__ dst,
                                                     int K, int N) {
    __shared__ float tile[32][33];
    const int tx = threadIdx.x & 31, ty = threadIdx.x >> 5;   // 32 x 8
    const int n0 = blockIdx.x * 32, k0 = blockIdx.y * 32;
#pragma unroll
    for (int i = 0; i < 4; ++i) {
        int k = k0 + ty + i * 8, n = n0 + tx;
        tile[ty + i * 8][tx] = (n < N) ? src[(size_t)k * N + n] : 0.f;
    }
    __syncthreads();
#pragma unroll
    for (int i = 0; i < 4; ++i) {
        int n = n0 + ty + i * 8, k = k0 + tx;
        dst[(size_t)n * K + k] = __float2half_rn(tile[tx][ty + i * 8]);
    }
}

// ---------------- HMMA fp16 GEMM ----------------
// C = act(A @ B^T + bias), fp16 in, fp16 out. CTA tile 128x128, K-chunk 64,
// 3-stage cp.async pipeline (A|B @ 16KB each = 32KB/stage).
static constexpr int STAGE_BYTES = 32768;
static constexpr int GEMM_SMEM   = 3 * STAGE_BYTES;      // 96 KB

template <bool WITH_NSQ>   // true: no relu + write norm partials; false: relu
__global__ __launch_bounds__(256, 2)
void hmma_gemm(const __half* __restrict__ Af, const __half* __restrict__ Bf,
               const float* __restrict__ bias,
               __half* __restrict__ C,
               int M, int K, int ldc, int nbias)
{
    extern __shared__ __align__(128) uint8_t smem[];
    const uint32_t sbase = smem_to_u32(smem);
    const int tid  = threadIdx.x;
    const int lane = tid & 31;
    const int wid  = tid >> 5;
    const int wm   = wid >> 2;          // 0..1  (m block of 64)
    const int wn   = wid & 3;           // 0..3  (n block of 32)
    const int m0   = blockIdx.y * 128;
    const int n0   = blockIdx.x * 128;

    const int lmat  = lane >> 3;
    const int lrow8 = ((lmat & 1) << 3) + (lane & 7);
    const int lchb  = lmat >> 1;        // 16B chunk parity within a k16

    float acc[4][4][4];
#pragma unroll
    for (int a = 0; a < 4; ++a)
#pragma unroll
        for (int b = 0; b < 4; ++b)
#pragma unroll
            for (int c = 0; c < 4; ++c) acc[a][b][c] = 0.f;

    auto load_stage = [&](int s, int k0) {
        const uint32_t base = sbase + s * STAGE_BYTES;
#pragma unroll
        for (int p = 0; p < 4; ++p) {
            int idx = p * 256 + tid;            // 0..1023
            int row = idx >> 3;                 // 0..127
            int ch  = idx & 7;                  // 16B chunk in 128B row
            uint32_t doff = swq(row, ch);
            int gm = m0 + row; if (gm > M - 1) gm = M - 1;   // clamp; rows >= M never stored
            CP16(base +         doff, Af + (size_t)gm * K + k0 + ch * 8);
            CP16(base + 16384 + doff, Bf + (size_t)(n0 + row) * K + k0 + ch * 8);
        }
        CP_COMMIT();
    };

    auto compute_stage = [&](int s) {
        const uint32_t base = sbase + s * STAGE_BYTES;
#pragma unroll
        for (int kh = 0; kh < 4; ++kh) {        // 4 x k16 per 64-chunk
            const int ch = kh * 2 + lchb;
            uint32_t bh[2][4], af[4][4];
#pragma unroll
            for (int np = 0; np < 2; ++np) {
                uint32_t addr = base + 16384 + swq(wn * 32 + np * 16 + lrow8, ch);
                LDSM4(bh[np][0], bh[np][1], bh[np][2], bh[np][3], addr);
            }
#pragma unroll
            for (int mt = 0; mt < 4; ++mt) {
                uint32_t addr = base + swq(wm * 64 + mt * 16 + lrow8, ch);
                LDSM4(af[mt][0], af[mt][1], af[mt][2], af[mt][3], addr);
            }
#pragma unroll
            for (int mt = 0; mt < 4; ++mt)
#pragma unroll
                for (int np = 0; np < 2; ++np)
#pragma unroll
                    for (int ni = 0; ni < 2; ++ni)
                        MMA_F16(acc[mt][np * 2 + ni],
                                af[mt][0], af[mt][1], af[mt][2], af[mt][3],
                                bh[np][ni], bh[np][ni + 2]);
        }
    };

    const int T = K >> 6;                 // GEMM1: 8, GEMM2: 16
    load_stage(0, 0);
    load_stage(1, 64);
    for (int t = 0; t < T; ++t) {
        CP_WAIT1();
        __syncthreads();
        if (t + 2 < T) load_stage((t + 2) % 3, (t + 2) << 6);
        else           CP_COMMIT();       // keep group count aligned for wait_group 1
        compute_stage(t % 3);
    }

    // ---------------- epilogue ----------------
    const int mbase = m0 + wm * 64 + (lane >> 2);
    const int nbase = n0 + wn * 32 + (lane & 3) * 2;
#pragma unroll
    for (int mt = 0; mt < 4; ++mt) {
        int m = mbase + mt * 16;
        float s0 = 0.f, s1 = 0.f;
#pragma unroll
        for (int nt = 0; nt < 4; ++nt) {
            int n = nbase + nt * 8;
            float b0 = (n     < nbias) ? __ldg(&bias[n])     : 0.f;
            float b1 = (n + 1 < nbias) ? __ldg(&bias[n + 1]) : 0.f;
            float v00 = acc[mt][nt][0] + b0, v01 = acc[mt][nt][1] + b1;
            float v10 = acc[mt][nt][2] + b0, v11 = acc[mt][nt][3] + b1;
            if (WITH_NSQ) {
                s0 += v00 * v00 + v01 * v01;
                s1 += v10 * v10 + v11 * v11;
            } else {
                v00 = fmaxf(v00, 0.f); v01 = fmaxf(v01, 0.f);
                v10 = fmaxf(v10, 0.f); v11 = fmaxf(v11, 0.f);
            }
            if (m < M)
                *reinterpret_cast<uint32_t*>(&C[(size_t)m * ldc + n]) = pack_h2(v00, v01);
            if (m + 8 < M)
                *reinterpret_cast<uint32_t*>(&C[(size_t)(m + 8) * ldc + n]) = pack_h2(v10, v11);
        }
        if (WITH_NSQ) {
            s0 += __shfl_xor_sync(0xffffffffu, s0, 1);
            s0 += __shfl_xor_sync(0xffffffffu, s0, 2);
            s1 += __shfl_xor_sync(0xffffffffu, s1, 1);
            s1 += __shfl_xor_sync(0xffffffffu, s1, 2);
            if ((lane & 3) == 0) {
                size_t slab = (size_t)(blockIdx.x * 4 + wn) * VROWS;
                if (m < M)     g_nsq[slab + m]     = s0;
                if (m + 8 < M) g_nsq[slab + m + 8] = s1;
            }
        }
    }
}

// ---------------- norm finalize + gather ----------------
__global__ __launch_bounds__(256) void rsqrt_kernel() {
    int r = blockIdx.x * 256 + threadIdx.x;
    if (r >= VOCAB) return;
    float tot = 0.f;
#pragma unroll
    for (int s = 0; s < NSLAB; ++s) tot += g_nsq[(size_t)s * VROWS + r];
    g_invnorm[r] = 1.f / fmaxf(sqrtf(tot), 1e-12f);
}

// out[b] = sum_{l<len} Eh[id] * invnorm[id]; each thread owns 8 consecutive cols.
// NOTE: out rows have stride 2047 floats -> NOT 16B aligned for odd b; scalar stores only.
__global__ __launch_bounds__(256) void gather_kernel(const int* __restrict__ ingrs,
                                                     const int* __restrict__ lengths,
                                                     float* __restrict__ out) {
    __shared__ const uint4* sptr[SEQ];
    __shared__ float sscl[SEQ];
    const int b = blockIdx.x;
    const int t = threadIdx.x;
    if (t < SEQ) {
        int id = ingrs[b * SEQ + t];
        sptr[t] = reinterpret_cast<const uint4*>(&g_Eh[(size_t)id * DOUTP]);
        sscl[t] = g_invnorm[id];
    }
    __syncthreads();
    int len = lengths[b];
    if (len > SEQ) len = SEQ;

    float acc[8] = {0.f,0.f,0.f,0.f,0.f,0.f,0.f,0.f};
    for (int l = 0; l < len; ++l) {
        const float s = sscl[l];
        uint4 v = __ldg(&sptr[l][t]);           // 8 halves, 16B-aligned (row stride 4KB)
        const __half2* h = reinterpret_cast<const __half2*>(&v);
#pragma unroll
        for (int q = 0; q < 4; ++q) {
            float2 f = __half22float2(h[q]);
            acc[q * 2]     += f.x * s;
            acc[q * 2 + 1] += f.y * s;
        }
    }
    float* o = out + (size_t)b * DOUT;
    const int c0 = t * 8;
    const int lim = DOUT - c0;                  // 2047 - c0; last thread writes 7
#pragma unroll
    for (int j = 0; j < 8; ++j)
        if (j < lim) o[c0 + j] = acc[j];
}

// ---------------- launch ----------------
extern "C" void kernel_launch(void* const* d_in, const int* in_sizes, int n_in,
                              void* d_out, int out_size)
{
    const int*   ingrs   = (const int*)  d_in[0];
    const int*   lengths = (const int*)  d_in[1];
    const float* W1      = (const float*)d_in[2];
    const float* b1      = (const float*)d_in[3];
    const float* W2      = (const float*)d_in[4];
    const float* b2      = (const float*)d_in[5];
    const float* W3      = (const float*)d_in[6];
    const float* b3      = (const float*)d_in[7];
    float* out = (float*)d_out;

    __half *h1f, *w2t, *w3t, *h2f, *eh;
    cudaGetSymbolAddress((void**)&h1f, g_H1f);
    cudaGetSymbolAddress((void**)&w2t, g_W2T);
    cudaGetSymbolAddress((void**)&w3t, g_W3T);
    cudaGetSymbolAddress((void**)&h2f, g_H2f);
    cudaGetSymbolAddress((void**)&eh,  g_Eh);

    cudaFuncSetAttribute(hmma_gemm<true>,  cudaFuncAttributeMaxDynamicSharedMemorySize, GEMM_SMEM);
    cudaFuncSetAttribute(hmma_gemm<false>, cudaFuncAttributeMaxDynamicSharedMemorySize, GEMM_SMEM);

    prep_h1<<<(VOCAB * DIN / 4 + 255) / 256, 256>>>(W1, b1);
    transpose_f16<<<dim3(DH / 32, DIN / 32), 256>>>(W2, w2t, DIN, DH);
    transpose_f16<<<dim3(DOUTP / 32, DH / 32), 256>>>(W3, w3t, DH, DOUT);

    // GEMM1: H2 = relu(H1 @ W2^T + b2)   [30000,1024] fp16
    dim3 g1(DH / 128, (VOCAB + 127) / 128);
    hmma_gemm<false><<<g1, 256, GEMM_SMEM>>>(h1f, w2t, b2, h2f, VOCAB, DIN, DH, DH);

    // GEMM2: E = H2 @ W3^T + b3          [30000,2048 padded] fp16 + fp32 norm partials
    dim3 g2(DOUTP / 128, (VOCAB + 127) / 128);
    hmma_gemm<true><<<g2, 256, GEMM_SMEM>>>(h2f, w3t, b3, eh, VOCAB, DH, DOUTP, DOUT);

    rsqrt_kernel<<<(VOCAB + 255) / 256, 256>>>();
    gather_kernel<<<NB, 256>>>(ingrs, lengths, out);
}

// round 8
// speedup vs baseline: 10.5197x; 1.0299x over previous
#include <cuda_runtime.h>
#include <cuda_fp16.h>
#include <cstdint>

#define VOCAB 30000
#define VROWS 30080          // padded row count for partial-norm slabs
#define DIN   512
#define DH    1024
#define DOUT  2047
#define DOUTP 2048
#define NB    4096
#define SEQ   20
#define NSLAB 64             // 16 N-tiles x 4 wn warps

// ---------------- scratch (__device__ globals; allocation-free rule) ----------------
__device__ __half g_H1f[(size_t)VOCAB * DIN];      // fp16
__device__ __half g_W2T[(size_t)DH * DIN];         // [1024,512] N-major fp16
__device__ __half g_W3T[(size_t)DOUTP * DH];       // [2048,1024] fp16, row 2047 zero
__device__ __half g_H2f[(size_t)VOCAB * DH];       // fp16
__device__ __half g_Eh[(size_t)VOCAB * DOUTP];     // fp16 E, padded col 2047 == 0
__device__ float  g_nsq[(size_t)NSLAB * VROWS];    // per-slab partial sum-of-squares (fp32)
__device__ float  g_invnorm[VOCAB];

// ---------------- PTX helpers (generic PTX only; valid at compute_103) ----------------
static __device__ __forceinline__ uint32_t smem_to_u32(const void* p) {
    uint32_t a;
    asm("{ .reg .u64 t; cvta.to.shared.u64 t, %1; cvt.u32.u64 %0, t; }" : "=r"(a) : "l"(p));
    return a;
}
#define CP16(dst, src) \
    asm volatile("cp.async.cg.shared.global [%0], [%1], 16;" :: "r"(dst), "l"(src) : "memory")
#define CP_COMMIT() asm volatile("cp.async.commit_group;" ::: "memory")
#define CP_WAIT1()  asm volatile("cp.async.wait_group 1;" ::: "memory")

#define LDSM4(r0, r1, r2, r3, addr) \
    asm volatile("ldmatrix.sync.aligned.m8n8.x4.shared.b16 {%0,%1,%2,%3}, [%4];" \
        : "=r"(r0), "=r"(r1), "=r"(r2), "=r"(r3) : "r"(addr))

#define MMA_F16(d, a0, a1, a2, a3, b0, b1) \
    asm volatile("mma.sync.aligned.m16n8k16.row.col.f32.f16.f16.f32 " \
        "{%0,%1,%2,%3},{%4,%5,%6,%7},{%8,%9},{%0,%1,%2,%3};" \
        : "+f"((d)[0]), "+f"((d)[1]), "+f"((d)[2]), "+f"((d)[3]) \
        : "r"(a0), "r"(a1), "r"(a2), "r"(a3), "r"(b0), "r"(b1))

// swizzled byte offset inside a 128-row x 128-byte tile (16KB): 8 chunks of 16B per row
static __device__ __forceinline__ uint32_t swq(int row, int ch) {
    return (uint32_t)(row * 128 + ((ch ^ (row & 7)) << 4));
}
static __device__ __forceinline__ uint32_t pack_h2(float x, float y) {
    __half2 h = __floats2half2_rn(x, y);
    return *reinterpret_cast<uint32_t*>(&h);
}

// ---------------- prep kernels ----------------
__global__ __launch_bounds__(256) void prep_h1(const float* __restrict__ W1,
                                               const float* __restrict__ b1) {
    size_t i4 = ((size_t)blockIdx.x * 256 + threadIdx.x) * 4;
    if (i4 >= (size_t)VOCAB * DIN) return;
    int k = (int)(i4 % DIN);
    float4 w  = *reinterpret_cast<const float4*>(&W1[i4]);
    float4 bb = *reinterpret_cast<const float4*>(&b1[k]);
    __half h[4] = { __float2half_rn(fmaxf(w.x + bb.x, 0.f)),
                    __float2half_rn(fmaxf(w.y + bb.y, 0.f)),
                    __float2half_rn(fmaxf(w.z + bb.z, 0.f)),
                    __float2half_rn(fmaxf(w.w + bb.w, 0.f)) };
    *reinterpret_cast<uint2*>(&g_H1f[i4]) = *reinterpret_cast<uint2*>(h);
}

// src [K][N] row-major fp32 -> dst [NP][K] fp16 (rows n>=N zero). Tiled transpose.
__global__ __launch_bounds__(256) void transpose_f16(const float* __restrict__ src,
                                                     __half* __restrict__ dst,
                                                     int K, int N) {
    __shared__ float tile[32][33];
    const int tx = threadIdx.x & 31, ty = threadIdx.x >> 5;   // 32 x 8
    const int n0 = blockIdx.x * 32, k0 = blockIdx.y * 32;
#pragma unroll
    for (int i = 0; i < 4; ++i) {
        int k = k0 + ty + i * 8, n = n0 + tx;
        tile[ty + i * 8][tx] = (n < N) ? src[(size_t)k * N + n] : 0.f;
    }
    __syncthreads();
#pragma unroll
    for (int i = 0; i < 4; ++i) {
        int n = n0 + ty + i * 8, k = k0 + tx;
        dst[(size_t)n * K + k] = __float2half_rn(tile[tx][ty + i * 8]);
    }
}

// ---------------- HMMA fp16 GEMM (register-double-buffered frags) ----------------
// C = act(A @ B^T + bias), fp16 in, fp16 out. CTA tile 128x128, K-chunk 64,
// 3-stage cp.async pipeline (A|B @ 16KB each = 32KB/stage).
static constexpr int STAGE_BYTES = 32768;
static constexpr int GEMM_SMEM   = 3 * STAGE_BYTES;      // 96 KB

template <bool WITH_NSQ>   // true: no relu + write norm partials; false: relu
__global__ __launch_bounds__(256, 2)
void hmma_gemm(const __half* __restrict__ Af, const __half* __restrict__ Bf,
               const float* __restrict__ bias,
               __half* __restrict__ C,
               int M, int K, int ldc, int nbias)
{
    extern __shared__ __align__(128) uint8_t smem[];
    const uint32_t sbase = smem_to_u32(smem);
    const int tid  = threadIdx.x;
    const int lane = tid & 31;
    const int wid  = tid >> 5;
    const int wm   = wid >> 2;          // 0..1  (m block of 64)
    const int wn   = wid & 3;           // 0..3  (n block of 32)
    const int m0   = blockIdx.y * 128;
    const int n0   = blockIdx.x * 128;

    const int lmat  = lane >> 3;
    const int lrow8 = ((lmat & 1) << 3) + (lane & 7);
    const int lchb  = lmat >> 1;        // 16B chunk parity within a k16

    float acc[4][4][4];
#pragma unroll
    for (int a = 0; a < 4; ++a)
#pragma unroll
        for (int b = 0; b < 4; ++b)
#pragma unroll
            for (int c = 0; c < 4; ++c) acc[a][b][c] = 0.f;

    auto load_stage = [&](int s, int k0) {
        const uint32_t base = sbase + s * STAGE_BYTES;
#pragma unroll
        for (int p = 0; p < 4; ++p) {
            int idx = p * 256 + tid;            // 0..1023
            int row = idx >> 3;                 // 0..127
            int ch  = idx & 7;                  // 16B chunk in 128B row
            uint32_t doff = swq(row, ch);
            int gm = m0 + row; if (gm > M - 1) gm = M - 1;   // clamp; rows >= M never stored
            CP16(base +         doff, Af + (size_t)gm * K + k0 + ch * 8);
            CP16(base + 16384 + doff, Bf + (size_t)(n0 + row) * K + k0 + ch * 8);
        }
        CP_COMMIT();
    };

    // fragment double buffers
    uint32_t afb[2][4][4], bhb[2][2][4];

    auto frag_load = [&](int set, uint32_t base, int kh) {
        const int ch = kh * 2 + lchb;
#pragma unroll
        for (int np = 0; np < 2; ++np) {
            uint32_t addr = base + 16384 + swq(wn * 32 + np * 16 + lrow8, ch);
            LDSM4(bhb[set][np][0], bhb[set][np][1], bhb[set][np][2], bhb[set][np][3], addr);
        }
#pragma unroll
        for (int mt = 0; mt < 4; ++mt) {
            uint32_t addr = base + swq(wm * 64 + mt * 16 + lrow8, ch);
            LDSM4(afb[set][mt][0], afb[set][mt][1], afb[set][mt][2], afb[set][mt][3], addr);
        }
    };
    auto frag_mma = [&](int set) {
#pragma unroll
        for (int mt = 0; mt < 4; ++mt)
#pragma unroll
            for (int np = 0; np < 2; ++np)
#pragma unroll
                for (int ni = 0; ni < 2; ++ni)
                    MMA_F16(acc[mt][np * 2 + ni],
                            afb[set][mt][0], afb[set][mt][1], afb[set][mt][2], afb[set][mt][3],
                            bhb[set][np][ni], bhb[set][np][ni + 2]);
    };

    const int T = K >> 6;                 // GEMM1: 8, GEMM2: 16
    load_stage(0, 0);
    load_stage(1, 64);
    CP_WAIT1();
    __syncthreads();                      // stage 0 resident
    uint32_t cbase = sbase;
    frag_load(0, cbase, 0);

    for (int t = 0; t < T; ++t) {
        if (t + 2 < T) load_stage((t + 2) % 3, (t + 2) << 6);
        else           CP_COMMIT();       // keep group count aligned for wait_group 1
#pragma unroll
        for (int kh = 0; kh < 4; ++kh) {
            if (kh < 3) frag_load((kh + 1) & 1, cbase, kh + 1);   // prefetch next k16
            frag_mma(kh & 1);
        }
        if (t + 1 < T) {
            CP_WAIT1();
            __syncthreads();              // stage t+1 resident
            cbase = sbase + ((t + 1) % 3) * STAGE_BYTES;
            frag_load(0, cbase, 0);
        }
    }

    // ---------------- epilogue ----------------
    const int mbase = m0 + wm * 64 + (lane >> 2);
    const int nbase = n0 + wn * 32 + (lane & 3) * 2;
#pragma unroll
    for (int mt = 0; mt < 4; ++mt) {
        int m = mbase + mt * 16;
        float s0 = 0.f, s1 = 0.f;
#pragma unroll
        for (int nt = 0; nt < 4; ++nt) {
            int n = nbase + nt * 8;
            float b0 = (n     < nbias) ? __ldg(&bias[n])     : 0.f;
            float b1 = (n + 1 < nbias) ? __ldg(&bias[n + 1]) : 0.f;
            float v00 = acc[mt][nt][0] + b0, v01 = acc[mt][nt][1] + b1;
            float v10 = acc[mt][nt][2] + b0, v11 = acc[mt][nt][3] + b1;
            if (WITH_NSQ) {
                s0 += v00 * v00 + v01 * v01;
                s1 += v10 * v10 + v11 * v11;
            } else {
                v00 = fmaxf(v00, 0.f); v01 = fmaxf(v01, 0.f);
                v10 = fmaxf(v10, 0.f); v11 = fmaxf(v11, 0.f);
            }
            if (m < M)
                *reinterpret_cast<uint32_t*>(&C[(size_t)m * ldc + n]) = pack_h2(v00, v01);
            if (m + 8 < M)
                *reinterpret_cast<uint32_t*>(&C[(size_t)(m + 8) * ldc + n]) = pack_h2(v10, v11);
        }
        if (WITH_NSQ) {
            s0 += __shfl_xor_sync(0xffffffffu, s0, 1);
            s0 += __shfl_xor_sync(0xffffffffu, s0, 2);
            s1 += __shfl_xor_sync(0xffffffffu, s1, 1);
            s1 += __shfl_xor_sync(0xffffffffu, s1, 2);
            if ((lane & 3) == 0) {
                size_t slab = (size_t)(blockIdx.x * 4 + wn) * VROWS;
                if (m < M)     g_nsq[slab + m]     = s0;
                if (m + 8 < M) g_nsq[slab + m + 8] = s1;
            }
        }
    }
}

// ---------------- norm finalize + gather ----------------
__global__ __launch_bounds__(256) void rsqrt_kernel() {
    int r = blockIdx.x * 256 + threadIdx.x;
    if (r >= VOCAB) return;
    float tot = 0.f;
#pragma unroll
    for (int s = 0; s < NSLAB; ++s) tot += g_nsq[(size_t)s * VROWS + r];
    g_invnorm[r] = 1.f / fmaxf(sqrtf(tot), 1e-12f);
}

// out[b] = sum_{l<len} Eh[id] * invnorm[id]; each thread owns 8 consecutive cols.
// NOTE: out rows have stride 2047 floats -> NOT 16B aligned for odd b; scalar stores only.
__global__ __launch_bounds__(256) void gather_kernel(const int* __restrict__ ingrs,
                                                     const int* __restrict__ lengths,
                                                     float* __restrict__ out) {
    __shared__ const uint4* sptr[SEQ];
    __shared__ float sscl[SEQ];
    const int b = blockIdx.x;
    const int t = threadIdx.x;
    if (t < SEQ) {
        int id = ingrs[b * SEQ + t];
        sptr[t] = reinterpret_cast<const uint4*>(&g_Eh[(size_t)id * DOUTP]);
        sscl[t] = g_invnorm[id];
    }
    __syncthreads();
    int len = lengths[b];
    if (len > SEQ) len = SEQ;

    float acc[8] = {0.f,0.f,0.f,0.f,0.f,0.f,0.f,0.f};
    for (int l = 0; l < len; ++l) {
        const float s = sscl[l];
        uint4 v = __ldg(&sptr[l][t]);           // 8 halves, 16B-aligned (row stride 4KB)
        const __half2* h = reinterpret_cast<const __half2*>(&v);
#pragma unroll
        for (int q = 0; q < 4; ++q) {
            float2 f = __half22float2(h[q]);
            acc[q * 2]     += f.x * s;
            acc[q * 2 + 1] += f.y * s;
        }
    }
    float* o = out + (size_t)b * DOUT;
    const int c0 = t * 8;
    const int lim = DOUT - c0;                  // last thread writes 7
#pragma unroll
    for (int j = 0; j < 8; ++j)
        if (j < lim) o[c0 + j] = acc[j];
}

// ---------------- launch ----------------
extern "C" void kernel_launch(void* const* d_in, const int* in_sizes, int n_in,
                              void* d_out, int out_size)
{
    const int*   ingrs   = (const int*)  d_in[0];
    const int*   lengths = (const int*)  d_in[1];
    const float* W1      = (const float*)d_in[2];
    const float* b1      = (const float*)d_in[3];
    const float* W2      = (const float*)d_in[4];
    const float* b2      = (const float*)d_in[5];
    const float* W3      = (const float*)d_in[6];
    const float* b3      = (const float*)d_in[7];
    float* out = (float*)d_out;

    __half *h1f, *w2t, *w3t, *h2f, *eh;
    cudaGetSymbolAddress((void**)&h1f, g_H1f);
    cudaGetSymbolAddress((void**)&w2t, g_W2T);
    cudaGetSymbolAddress((void**)&w3t, g_W3T);
    cudaGetSymbolAddress((void**)&h2f, g_H2f);
    cudaGetSymbolAddress((void**)&eh,  g_Eh);

    cudaFuncSetAttribute(hmma_gemm<true>,  cudaFuncAttributeMaxDynamicSharedMemorySize, GEMM_SMEM);
    cudaFuncSetAttribute(hmma_gemm<false>, cudaFuncAttributeMaxDynamicSharedMemorySize, GEMM_SMEM);

    prep_h1<<<(VOCAB * DIN / 4 + 255) / 256, 256>>>(W1, b1);
    transpose_f16<<<dim3(DH / 32, DIN / 32), 256>>>(W2, w2t, DIN, DH);
    transpose_f16<<<dim3(DOUTP / 32, DH / 32), 256>>>(W3, w3t, DH, DOUT);

    // GEMM1: H2 = relu(H1 @ W2^T + b2)   [30000,1024] fp16
    dim3 g1(DH / 128, (VOCAB + 127) / 128);
    hmma_gemm<false><<<g1, 256, GEMM_SMEM>>>(h1f, w2t, b2, h2f, VOCAB, DIN, DH, DH);

    // GEMM2: E = H2 @ W3^T + b3          [30000,2048 padded] fp16 + fp32 norm partials
    dim3 g2(DOUTP / 128, (VOCAB + 127) / 128);
    hmma_gemm<true><<<g2, 256, GEMM_SMEM>>>(h2f, w3t, b3, eh, VOCAB, DH, DOUTP, DOUT);

    rsqrt_kernel<<<(VOCAB + 255) / 256, 256>>>();
    gather_kernel<<<NB, 256>>>(ingrs, lengths, out);
}